// round 4
// baseline (speedup 1.0000x reference)
#include <cuda_runtime.h>
#include <cuda_bf16.h>
#include <cstdint>

// ---------------------------------------------------------------------------
// Problem: B=16, C=1024, H=W=32 (N=1024), T=77, NUM_HEADS=8, HD=128
// Pipeline:
//   KV = Wkv @ Tx + bkv            [b] : [2048x1024]@[1024x77]
//   Q  = Wq  @ Vx + bq             [b] : [1024x1024]@[1024x1024]
//   S  = scale * Q_h^T @ K_h       [b,h]: [1024x128]@[128x77]
//   P  = softmax_t(S)
//   O  = V_h @ P^T                 [b,h]: [128x77]@[77x1024]
//   Y  = Wp @ O + bp               [b] : [1024x1024]@[1024x1024]
// KV head split (reshape (b,8,256,77)): K_h rows = [256h,256h+128),
// V_h rows = [256h+128, 256h+256).
// ---------------------------------------------------------------------------

#define NB 16
#define CC 1024
#define NN 1024
#define TT 77
#define TP 80          // padded T for scratch rows
#define NH 8
#define HD 128

// Scratch (device globals: no allocation allowed)
__device__ float g_Q [(size_t)NB * CC * NN];          // 64 MB
__device__ float g_KV[(size_t)NB * 2 * CC * TP];      // 10.5 MB
__device__ float g_S [(size_t)NB * NH * NN * TP];     // 42 MB
__device__ float g_O [(size_t)NB * CC * NN];          // 64 MB

__device__ __forceinline__ uint32_t f2tf32(float x) {
    uint32_t r;
    asm("cvt.rna.tf32.f32 %0, %1;" : "=r"(r) : "f"(x));
    return r;
}

__device__ __forceinline__ void mma_tf32(float* c, const uint32_t* a, const uint32_t* b) {
    asm volatile(
        "mma.sync.aligned.m16n8k8.row.col.f32.tf32.tf32.f32 "
        "{%0,%1,%2,%3}, {%4,%5,%6,%7}, {%8,%9}, {%0,%1,%2,%3};\n"
        : "+f"(c[0]), "+f"(c[1]), "+f"(c[2]), "+f"(c[3])
        : "r"(a[0]), "r"(a[1]), "r"(a[2]), "r"(a[3]), "r"(b[0]), "r"(b[1]));
}

// Generic batched TF32 GEMM:
//   C[z][m,n] = alpha * sum_k A[z][m,k] * B[z][k,n] + bias[m]
//   A[z][m,k] at A + b*sAb + h*sAh + m*sAm + k*sAk   (z = b*nh + h)
//   B[z][k,n] at B + b*sBb + h*sBh + k*sBk + n*sBn
//   C[z][m,n] at C + b*sCb + h*sCh + m*ldc + n
// Requires M % 128 == 0. N,K arbitrary (zero-padded tiles).
// A_KMAJ: sAk==1 (load k-fastest);  B_NMAJ: sBn==1 (load n-fastest).
template <bool A_KMAJ, bool B_NMAJ>
__global__ __launch_bounds__(256, 2)
void gemm_tf32(const float* __restrict__ A, const float* __restrict__ B,
               float* __restrict__ C, const float* __restrict__ bias,
               int M, int N, int K,
               long long sAm, long long sAk, long long sBk, long long sBn,
               long long ldc,
               long long sAb, long long sAh, long long sBb, long long sBh,
               long long sCb, long long sCh, int nh, float alpha)
{
    constexpr int BM = 128, BN = 128, BK = 32;
    __shared__ uint32_t As[BM][BK + 4];   // [m][k] : store & frag-load conflict-free
    __shared__ uint32_t Bs[BK][BN + 8];   // [k][n] : store & frag-load conflict-free

    const int tid  = threadIdx.x;
    const int lane = tid & 31;
    const int warp = tid >> 5;
    const int wm = (warp & 3) * 32;   // 4 warps along M
    const int wn = (warp >> 2) * 64;  // 2 warps along N
    const int gid = lane >> 2;        // group id (0..7)
    const int tig = lane & 3;         // thread-in-group (0..3)

    const int z = blockIdx.z;
    const int b = z / nh;
    const int h = z - b * nh;
    const float* Ab = A + (size_t)b * sAb + (size_t)h * sAh;
    const float* Bb = B + (size_t)b * sBb + (size_t)h * sBh;
    float*       Cb = C + (size_t)b * sCb + (size_t)h * sCh;

    const int m0 = blockIdx.y * BM;
    const int n0 = blockIdx.x * BN;

    float acc[2][8][4];
    #pragma unroll
    for (int mi = 0; mi < 2; mi++)
        #pragma unroll
        for (int ni = 0; ni < 8; ni++)
            #pragma unroll
            for (int j = 0; j < 4; j++) acc[mi][ni][j] = 0.f;

    const int ktiles = (K + BK - 1) / BK;
    for (int kt = 0; kt < ktiles; kt++) {
        const int k0 = kt * BK;
        // ---- load A tile (BM x BK) ----
        #pragma unroll
        for (int i = 0; i < (BM * BK) / 256; i++) {
            int idx = tid + i * 256;
            int m, k;
            if (A_KMAJ) { m = idx >> 5; k = idx & 31; }
            else        { k = idx >> 7; m = idx & 127; }
            int kg = k0 + k;
            float v = (kg < K) ? Ab[(size_t)(m0 + m) * sAm + (size_t)kg * sAk] : 0.f;
            As[m][k] = f2tf32(v);
        }
        // ---- load B tile (BK x BN) ----
        #pragma unroll
        for (int i = 0; i < (BK * BN) / 256; i++) {
            int idx = tid + i * 256;
            int k, n;
            if (B_NMAJ) { k = idx >> 7; n = idx & 127; }
            else        { n = idx >> 5; k = idx & 31; }
            int kg = k0 + k;
            int ng = n0 + n;
            float v = (kg < K && ng < N) ? Bb[(size_t)kg * sBk + (size_t)ng * sBn] : 0.f;
            Bs[k][n] = f2tf32(v);
        }
        __syncthreads();

        #pragma unroll
        for (int kk = 0; kk < BK; kk += 8) {
            uint32_t afr[2][4], bfr[8][2];
            #pragma unroll
            for (int mi = 0; mi < 2; mi++) {
                int r = wm + mi * 16 + gid;
                afr[mi][0] = As[r][kk + tig];
                afr[mi][1] = As[r + 8][kk + tig];
                afr[mi][2] = As[r][kk + tig + 4];
                afr[mi][3] = As[r + 8][kk + tig + 4];
            }
            #pragma unroll
            for (int ni = 0; ni < 8; ni++) {
                int cn = wn + ni * 8 + gid;
                bfr[ni][0] = Bs[kk + tig][cn];
                bfr[ni][1] = Bs[kk + tig + 4][cn];
            }
            #pragma unroll
            for (int mi = 0; mi < 2; mi++)
                #pragma unroll
                for (int ni = 0; ni < 8; ni++)
                    mma_tf32(acc[mi][ni], afr[mi], bfr[ni]);
        }
        __syncthreads();
    }

    // ---- epilogue ----
    #pragma unroll
    for (int mi = 0; mi < 2; mi++) {
        int r0 = m0 + wm + mi * 16 + gid;
        float bv0 = bias ? bias[r0]     : 0.f;
        float bv1 = bias ? bias[r0 + 8] : 0.f;
        #pragma unroll
        for (int ni = 0; ni < 8; ni++) {
            int c0 = n0 + wn + ni * 8 + 2 * tig;
            if (c0 < N) {
                Cb[(size_t)r0 * ldc + c0]       = alpha * acc[mi][ni][0] + bv0;
                Cb[(size_t)(r0 + 8) * ldc + c0] = alpha * acc[mi][ni][2] + bv1;
            }
            if (c0 + 1 < N) {
                Cb[(size_t)r0 * ldc + c0 + 1]       = alpha * acc[mi][ni][1] + bv0;
                Cb[(size_t)(r0 + 8) * ldc + c0 + 1] = alpha * acc[mi][ni][3] + bv1;
            }
        }
    }
}

// Row-wise softmax over 77 valid columns of an 80-wide row. One warp per row.
__global__ void softmax77(float* __restrict__ S)
{
    int row  = blockIdx.x * 4 + (threadIdx.x >> 5);
    int lane = threadIdx.x & 31;
    float* p = S + (size_t)row * TP;

    float x0 = p[lane];
    float x1 = (lane + 32 < TT) ? p[lane + 32] : -1e30f;
    float x2 = (lane + 64 < TT) ? p[lane + 64] : -1e30f;
    float m = fmaxf(x0, fmaxf(x1, x2));
    #pragma unroll
    for (int off = 16; off > 0; off >>= 1)
        m = fmaxf(m, __shfl_xor_sync(0xFFFFFFFFu, m, off));
    float e0 = __expf(x0 - m);
    float e1 = (lane + 32 < TT) ? __expf(x1 - m) : 0.f;
    float e2 = (lane + 64 < TT) ? __expf(x2 - m) : 0.f;
    float s = e0 + e1 + e2;
    #pragma unroll
    for (int off = 16; off > 0; off >>= 1)
        s += __shfl_xor_sync(0xFFFFFFFFu, s, off);
    float inv = 1.f / s;
    p[lane] = e0 * inv;
    if (lane + 32 < TT) p[lane + 32] = e1 * inv;
    if (lane + 64 < TT) p[lane + 64] = e2 * inv;
}

extern "C" void kernel_launch(void* const* d_in, const int* in_sizes, int n_in,
                              void* d_out, int out_size)
{
    const float* Vx  = (const float*)d_in[0];
    const float* Tx  = (const float*)d_in[1];
    const float* Wq  = (const float*)d_in[2];
    const float* bq  = (const float*)d_in[3];
    const float* Wkv = (const float*)d_in[4];
    const float* bkv = (const float*)d_in[5];
    const float* Wp  = (const float*)d_in[6];
    const float* bp  = (const float*)d_in[7];
    float* Y = (float*)d_out;

    float *Q, *KV, *S, *O;
    cudaGetSymbolAddress((void**)&Q,  g_Q);
    cudaGetSymbolAddress((void**)&KV, g_KV);
    cudaGetSymbolAddress((void**)&S,  g_S);
    cudaGetSymbolAddress((void**)&O,  g_O);

    const float scale = 0.08838834764831843f;  // 1/sqrt(128)

    // 1) KV = Wkv @ Tx + bkv : per-b, M=2048, N=77, K=1024
    gemm_tf32<true, true><<<dim3(1, 16, NB), 256>>>(
        Wkv, Tx, KV, bkv, 2048, TT, CC,
        /*sAm*/CC, /*sAk*/1, /*sBk*/TT, /*sBn*/1, /*ldc*/TP,
        /*sAb*/0, /*sAh*/0, /*sBb*/(long long)CC * TT, /*sBh*/0,
        /*sCb*/(long long)2 * CC * TP, /*sCh*/0, 1, 1.0f);

    // 2) Q = Wq @ Vx + bq : per-b, M=1024, N=1024, K=1024
    gemm_tf32<true, true><<<dim3(8, 8, NB), 256>>>(
        Wq, Vx, Q, bq, CC, NN, CC,
        CC, 1, NN, 1, NN,
        0, 0, (long long)CC * NN, 0,
        (long long)CC * NN, 0, 1, 1.0f);

    // 3) S = scale * Q_h^T @ K_h : per-(b,h), M=1024(n), N=77(t), K=128(d)
    //    A[m,k] = Q[b][h*128 + k][m]  (m-fastest) ; B[k,n] = KV[b][h*256 + k][n]
    gemm_tf32<false, true><<<dim3(1, 8, NB * NH), 256>>>(
        Q, KV, S, nullptr, NN, TT, HD,
        /*sAm*/1, /*sAk*/NN, /*sBk*/TP, /*sBn*/1, /*ldc*/TP,
        /*sAb*/(long long)CC * NN, /*sAh*/(long long)HD * NN,
        /*sBb*/(long long)2 * CC * TP, /*sBh*/(long long)2 * HD * TP,
        /*sCb*/(long long)NH * NN * TP, /*sCh*/(long long)NN * TP,
        NH, scale);

    // 4) P = softmax_t(S) : 16*8*1024 rows
    softmax77<<<(NB * NH * NN) / 4, 128>>>(S);

    // 5) O = V_h @ P^T : per-(b,h), M=128(d), N=1024(n), K=77(t)
    //    A[m,k] = KV[b][h*256 + 128 + m][k] ; B[k,n] = P[z][n*80 + k]
    gemm_tf32<true, false><<<dim3(8, 1, NB * NH), 256>>>(
        KV + (size_t)HD * TP, S, O, nullptr, HD, NN, TT,
        /*sAm*/TP, /*sAk*/1, /*sBk*/1, /*sBn*/TP, /*ldc*/NN,
        /*sAb*/(long long)2 * CC * TP, /*sAh*/(long long)2 * HD * TP,
        /*sBb*/(long long)NH * NN * TP, /*sBh*/(long long)NN * TP,
        /*sCb*/(long long)CC * NN, /*sCh*/(long long)HD * NN,
        NH, 1.0f);

    // 6) Y = Wp @ O + bp : per-b, M=1024, N=1024, K=1024
    gemm_tf32<true, true><<<dim3(8, 8, NB), 256>>>(
        Wp, O, Y, bp, CC, NN, CC,
        CC, 1, NN, 1, NN,
        0, 0, (long long)CC * NN, 0,
        (long long)CC * NN, 0, 1, 1.0f);
}

// round 6
// speedup vs baseline: 1.7241x; 1.7241x over previous
#include <cuda_runtime.h>
#include <cuda_bf16.h>
#include <cstdint>

// ---------------------------------------------------------------------------
// B=16, C=1024, N=H*W=1024, T=77, heads=8, hd=128
//   KV = Wkv @ Tx + bkv
//   Q  = Wq  @ Vx + bq
//   S  = scale * Q_h^T K_h
//   P  = softmax_t(S)
//   O  = V_h @ P^T
//   Y  = Wp @ O + bp
// All GEMMs: mma.sync tf32 (tcgen05 rejected by toolchain: PTX target is
// sm_103 without 'a'), 3-stage cp.async pipeline, 128x128x32 tiles.
// KV head split: K_h rows [256h,256h+128), V_h rows [256h+128,256h+256).
// Scratch cols 77..79 (pitch 80) are never written => stay zero => safe reads.
// ---------------------------------------------------------------------------

#define NB 16
#define CC 1024
#define NN 1024
#define TT 77
#define TP 80
#define NH 8
#define HD 128

__device__ float g_Q [(size_t)NB * CC * NN];
__device__ float g_KV[(size_t)NB * 2 * CC * TP];
__device__ float g_S [(size_t)NB * NH * NN * TP];
__device__ float g_O [(size_t)NB * CC * NN];

__device__ __forceinline__ uint32_t smem_u32(const void* p) {
    uint32_t a;
    asm("{ .reg .u64 t; cvta.to.shared.u64 t, %1; cvt.u32.u64 %0, t; }" : "=r"(a) : "l"(p));
    return a;
}
__device__ __forceinline__ uint32_t f2tf32(float x) {
    uint32_t r;
    asm("cvt.rna.tf32.f32 %0, %1;" : "=r"(r) : "f"(x));
    return r;
}
__device__ __forceinline__ void mma_tf32(float* c, const uint32_t* a, const uint32_t* b) {
    asm volatile(
        "mma.sync.aligned.m16n8k8.row.col.f32.tf32.tf32.f32 "
        "{%0,%1,%2,%3}, {%4,%5,%6,%7}, {%8,%9}, {%0,%1,%2,%3};\n"
        : "+f"(c[0]), "+f"(c[1]), "+f"(c[2]), "+f"(c[3])
        : "r"(a[0]), "r"(a[1]), "r"(a[2]), "r"(a[3]), "r"(b[0]), "r"(b[1]));
}

#define CP16(d, s, sz) asm volatile("cp.async.cg.shared.global [%0], [%1], 16, %2;" :: "r"(d), "l"(s), "r"(sz) : "memory")
#define CP4(d, s, sz)  asm volatile("cp.async.ca.shared.global [%0], [%1], 4, %2;"  :: "r"(d), "l"(s), "r"(sz) : "memory")
#define CP_COMMIT()    asm volatile("cp.async.commit_group;" ::: "memory")
#define CP_WAIT1()     asm volatile("cp.async.wait_group 1;" ::: "memory")

// Pipelined batched TF32 GEMM. C[z][m,n] = alpha*sum_k A.B + bias[m].
//   A_KMAJ: A contiguous along k (sAk==1); else contiguous along m (sAm==1).
//   B_NMAJ: B contiguous along n (sBn==1); else contiguous along k (sBk==1).
//   B_VEC : B contiguous rows are 16B-aligned (use 16B cp.async).
//   Ka    : A k-read bound (reads k<Ka are in-bounds; zeros beyond valid K).
//   Bbound: B contiguous-dim read bound (n-bound if B_NMAJ else k-bound).
// Requires M % 128 == 0.
template <bool A_KMAJ, bool B_NMAJ, bool B_VEC>
__global__ __launch_bounds__(256, 2)
void gemm_pipe(const float* __restrict__ A, const float* __restrict__ B,
               float* __restrict__ C, const float* __restrict__ bias,
               int M, int N, int K,
               long long sAm, long long sAk, long long sBk, long long sBn,
               long long ldc,
               long long sAb, long long sAh, long long sBb, long long sBh,
               long long sCb, long long sCh, int nh, float alpha,
               int Ka, int Bbound)
{
    constexpr int A_FLOATS = 4608;               // max(128*36, 32*136)
    constexpr int B_FLOATS = 4608;               // max(32*132, 128*36)
    constexpr int STAGE_F  = A_FLOATS + B_FLOATS;

    extern __shared__ float smem[];
    const uint32_t sb = smem_u32(smem);

    const int tid  = threadIdx.x;
    const int lane = tid & 31;
    const int warp = tid >> 5;
    const int wm = (warp & 3) * 32;
    const int wn = (warp >> 2) * 64;
    const int gid = lane >> 2;
    const int tig = lane & 3;

    const int z = blockIdx.z;
    const int b = z / nh;
    const int h = z - b * nh;
    const float* Ab = A + (size_t)b * sAb + (size_t)h * sAh;
    const float* Bb = B + (size_t)b * sBb + (size_t)h * sBh;
    float*       Cb = C + (size_t)b * sCb + (size_t)h * sCh;

    const int m0 = blockIdx.y * 128;
    const int n0 = blockIdx.x * 128;
    const int nkt = (K + 31) >> 5;

    // ---- stage loader (cp.async) ----
    auto load_tile = [&](int kt, int s) {
        const int k0 = kt << 5;
        const uint32_t aB = sb + (uint32_t)(s * STAGE_F) * 4u;
        const uint32_t bB = aB + (uint32_t)A_FLOATS * 4u;
        // A tile
        #pragma unroll
        for (int i = 0; i < 4; i++) {
            int c = tid + i * 256;
            if (A_KMAJ) {
                int m = c >> 3, seg = c & 7;                 // [128m][32k] -> [m][36]
                const float* src = Ab + (size_t)(m0 + m) * sAm + k0 + (seg << 2);
                uint32_t dst = aB + (uint32_t)(m * 36 + (seg << 2)) * 4u;
                int sz = (k0 + (seg << 2) < Ka) ? 16 : 0;
                CP16(dst, src, sz);
            } else {
                int k = c >> 5, ms = c & 31;                 // [32k][128m] -> [k][136]
                const float* src = Ab + (size_t)(k0 + k) * sAk + m0 + (ms << 2);
                uint32_t dst = aB + (uint32_t)(k * 136 + (ms << 2)) * 4u;
                int sz = (k0 + k < Ka) ? 16 : 0;
                CP16(dst, src, sz);
            }
        }
        // B tile
        if (B_NMAJ) {
            if (B_VEC) {
                #pragma unroll
                for (int i = 0; i < 4; i++) {
                    int c = tid + i * 256;
                    int k = c >> 5, ns = c & 31;             // [32k][128n] -> [k][132]
                    const float* src = Bb + (size_t)(k0 + k) * sBk + n0 + (ns << 2);
                    uint32_t dst = bB + (uint32_t)(k * 132 + (ns << 2)) * 4u;
                    int sz = (n0 + (ns << 2) < Bbound) ? 16 : 0;
                    CP16(dst, src, sz);
                }
            } else {
                #pragma unroll
                for (int i = 0; i < 16; i++) {
                    int e = tid + i * 256;
                    int k = e >> 7, n = e & 127;
                    const float* src = Bb + (size_t)(k0 + k) * sBk + n0 + n;
                    uint32_t dst = bB + (uint32_t)(k * 132 + n) * 4u;
                    int sz = (n0 + n < Bbound) ? 4 : 0;
                    CP4(dst, src, sz);
                }
            }
        } else {
            #pragma unroll
            for (int i = 0; i < 4; i++) {
                int c = tid + i * 256;
                int n = c >> 3, seg = c & 7;                 // [128n][32k] -> [n][36]
                const float* src = Bb + (size_t)(n0 + n) * sBn + k0 + (seg << 2);
                uint32_t dst = bB + (uint32_t)(n * 36 + (seg << 2)) * 4u;
                int sz = (k0 + (seg << 2) < Bbound) ? 16 : 0;
                CP16(dst, src, sz);
            }
        }
        CP_COMMIT();
    };

    float acc[2][8][4];
    #pragma unroll
    for (int mi = 0; mi < 2; mi++)
        #pragma unroll
        for (int ni = 0; ni < 8; ni++)
            #pragma unroll
            for (int j = 0; j < 4; j++) acc[mi][ni][j] = 0.f;

    // prologue: stages 0,1
    load_tile(0, 0);
    load_tile(1, 1);

    for (int kt = 0; kt < nkt; kt++) {
        CP_WAIT1();
        __syncthreads();
        // prefetch kt+2
        if (kt + 2 < nkt) load_tile(kt + 2, (kt + 2) % 3);
        else CP_COMMIT();

        const float* As = smem + (kt % 3) * STAGE_F;
        const float* Bs = As + A_FLOATS;

        #pragma unroll
        for (int kk = 0; kk < 32; kk += 8) {
            uint32_t afr[2][4], bfr[8][2];
            #pragma unroll
            for (int mi = 0; mi < 2; mi++) {
                int r = wm + mi * 16 + gid;
                if (A_KMAJ) {
                    afr[mi][0] = f2tf32(As[r * 36 + kk + tig]);
                    afr[mi][1] = f2tf32(As[(r + 8) * 36 + kk + tig]);
                    afr[mi][2] = f2tf32(As[r * 36 + kk + tig + 4]);
                    afr[mi][3] = f2tf32(As[(r + 8) * 36 + kk + tig + 4]);
                } else {
                    afr[mi][0] = f2tf32(As[(kk + tig) * 136 + r]);
                    afr[mi][1] = f2tf32(As[(kk + tig) * 136 + r + 8]);
                    afr[mi][2] = f2tf32(As[(kk + tig + 4) * 136 + r]);
                    afr[mi][3] = f2tf32(As[(kk + tig + 4) * 136 + r + 8]);
                }
            }
            #pragma unroll
            for (int ni = 0; ni < 8; ni++) {
                int cn = wn + ni * 8 + gid;
                if (B_NMAJ) {
                    bfr[ni][0] = f2tf32(Bs[(kk + tig) * 132 + cn]);
                    bfr[ni][1] = f2tf32(Bs[(kk + tig + 4) * 132 + cn]);
                } else {
                    bfr[ni][0] = f2tf32(Bs[cn * 36 + kk + tig]);
                    bfr[ni][1] = f2tf32(Bs[cn * 36 + kk + tig + 4]);
                }
            }
            #pragma unroll
            for (int mi = 0; mi < 2; mi++)
                #pragma unroll
                for (int ni = 0; ni < 8; ni++)
                    mma_tf32(acc[mi][ni], afr[mi], bfr[ni]);
        }
    }

    // ---- epilogue ----
    #pragma unroll
    for (int mi = 0; mi < 2; mi++) {
        int r0 = m0 + wm + mi * 16 + gid;
        float bv0 = bias ? bias[r0]     : 0.f;
        float bv1 = bias ? bias[r0 + 8] : 0.f;
        #pragma unroll
        for (int ni = 0; ni < 8; ni++) {
            int c0 = n0 + wn + ni * 8 + 2 * tig;
            if (c0 < N) {
                Cb[(size_t)r0 * ldc + c0]       = alpha * acc[mi][ni][0] + bv0;
                Cb[(size_t)(r0 + 8) * ldc + c0] = alpha * acc[mi][ni][2] + bv1;
            }
            if (c0 + 1 < N) {
                Cb[(size_t)r0 * ldc + c0 + 1]       = alpha * acc[mi][ni][1] + bv0;
                Cb[(size_t)(r0 + 8) * ldc + c0 + 1] = alpha * acc[mi][ni][3] + bv1;
            }
        }
    }
}

// Row-wise softmax over 77 valid cols of an 80-wide row; one warp per row.
__global__ void softmax77(float* __restrict__ S)
{
    int row  = blockIdx.x * 4 + (threadIdx.x >> 5);
    int lane = threadIdx.x & 31;
    float* p = S + (size_t)row * TP;

    float x0 = p[lane];
    float x1 = (lane + 32 < TT) ? p[lane + 32] : -1e30f;
    float x2 = (lane + 64 < TT) ? p[lane + 64] : -1e30f;
    float m = fmaxf(x0, fmaxf(x1, x2));
    #pragma unroll
    for (int off = 16; off > 0; off >>= 1)
        m = fmaxf(m, __shfl_xor_sync(0xFFFFFFFFu, m, off));
    float e0 = __expf(x0 - m);
    float e1 = (lane + 32 < TT) ? __expf(x1 - m) : 0.f;
    float e2 = (lane + 64 < TT) ? __expf(x2 - m) : 0.f;
    float s = e0 + e1 + e2;
    #pragma unroll
    for (int off = 16; off > 0; off >>= 1)
        s += __shfl_xor_sync(0xFFFFFFFFu, s, off);
    float inv = 1.f / s;
    p[lane] = e0 * inv;
    if (lane + 32 < TT) p[lane + 32] = e1 * inv;
    if (lane + 64 < TT) p[lane + 64] = e2 * inv;
}

extern "C" void kernel_launch(void* const* d_in, const int* in_sizes, int n_in,
                              void* d_out, int out_size)
{
    const float* Vx  = (const float*)d_in[0];
    const float* Tx  = (const float*)d_in[1];
    const float* Wq  = (const float*)d_in[2];
    const float* bq  = (const float*)d_in[3];
    const float* Wkv = (const float*)d_in[4];
    const float* bkv = (const float*)d_in[5];
    const float* Wp  = (const float*)d_in[6];
    const float* bp  = (const float*)d_in[7];
    float* Y = (float*)d_out;

    float *Q, *KV, *S, *O;
    cudaGetSymbolAddress((void**)&Q,  g_Q);
    cudaGetSymbolAddress((void**)&KV, g_KV);
    cudaGetSymbolAddress((void**)&S,  g_S);
    cudaGetSymbolAddress((void**)&O,  g_O);

    constexpr int SMEM_BYTES = (4608 + 4608) * 3 * 4;  // 110592
    cudaFuncSetAttribute(gemm_pipe<true, true, true>,
                         cudaFuncAttributeMaxDynamicSharedMemorySize, SMEM_BYTES);
    cudaFuncSetAttribute(gemm_pipe<true, true, false>,
                         cudaFuncAttributeMaxDynamicSharedMemorySize, SMEM_BYTES);
    cudaFuncSetAttribute(gemm_pipe<false, true, true>,
                         cudaFuncAttributeMaxDynamicSharedMemorySize, SMEM_BYTES);
    cudaFuncSetAttribute(gemm_pipe<true, false, true>,
                         cudaFuncAttributeMaxDynamicSharedMemorySize, SMEM_BYTES);

    const float scale = 0.08838834764831843f;  // 1/sqrt(128)

    // 1) KV = Wkv @ Tx + bkv : per-b, M=2048, N=77, K=1024 (B rows not 16B-aligned)
    gemm_pipe<true, true, false><<<dim3(1, 16, NB), 256, SMEM_BYTES>>>(
        Wkv, Tx, KV, bkv, 2048, TT, CC,
        CC, 1, TT, 1, TP,
        0, 0, (long long)CC * TT, 0,
        (long long)2 * CC * TP, 0, 1, 1.0f, CC, TT);

    // 2) Q = Wq @ Vx + bq : per-b, M=1024, N=1024, K=1024
    gemm_pipe<true, true, true><<<dim3(8, 8, NB), 256, SMEM_BYTES>>>(
        Wq, Vx, Q, bq, CC, NN, CC,
        CC, 1, NN, 1, NN,
        0, 0, (long long)CC * NN, 0,
        (long long)CC * NN, 0, 1, 1.0f, CC, NN);

    // 3) S = scale * Q_h^T @ K_h : per-(b,h), M=1024(n), N=77(t), K=128(d)
    gemm_pipe<false, true, true><<<dim3(1, 8, NB * NH), 256, SMEM_BYTES>>>(
        Q, KV, S, nullptr, NN, TT, HD,
        1, NN, TP, 1, TP,
        (long long)CC * NN, (long long)HD * NN,
        (long long)2 * CC * TP, (long long)2 * HD * TP,
        (long long)NH * NN * TP, (long long)NN * TP,
        NH, scale, HD, TP);

    // 4) softmax
    softmax77<<<(NB * NH * NN) / 4, 128>>>(S);

    // 5) O = V_h @ P^T : per-(b,h), M=128(d), N=1024(n), K=77(t)
    gemm_pipe<true, false, true><<<dim3(8, 1, NB * NH), 256, SMEM_BYTES>>>(
        KV + (size_t)HD * TP, S, O, nullptr, HD, NN, TT,
        TP, 1, 1, TP, NN,
        (long long)2 * CC * TP, (long long)2 * HD * TP,
        (long long)NH * NN * TP, (long long)NN * TP,
        (long long)CC * NN, (long long)HD * NN,
        NH, 1.0f, TP, TP);

    // 6) Y = Wp @ O + bp : per-b, M=1024, N=1024, K=1024
    gemm_pipe<true, true, true><<<dim3(8, 8, NB), 256, SMEM_BYTES>>>(
        Wp, O, Y, bp, CC, NN, CC,
        CC, 1, NN, 1, NN,
        0, 0, (long long)CC * NN, 0,
        (long long)CC * NN, 0, 1, 1.0f, CC, NN);
}

// round 7
// speedup vs baseline: 2.0482x; 1.1879x over previous
#include <cuda_runtime.h>
#include <cuda_fp16.h>
#include <cstdint>

// ---------------------------------------------------------------------------
// B=16, C=1024, N=1024, T=77(pad 80), heads=8, hd=128.  All GEMMs fp16
// mma.sync.m16n8k16 (fp32 accum) + ldmatrix + 3-stage cp.async.
// Softmax fused into S-GEMM epilogue. Scratch fp16; cols 77..79 stored zero.
// KV head split: K_h rows [256h,256h+128), V_h rows [256h+128,256h+256).
// ---------------------------------------------------------------------------

#define NB 16
#define CC 1024
#define NN 1024
#define TT 77
#define TP 80
#define NH 8
#define HD 128

__device__ __half h_Vx[(size_t)NB * CC * NN];
__device__ __half h_Tx[(size_t)NB * CC * TP];
__device__ __half h_Wq[(size_t)CC * CC];
__device__ __half h_Wkv[(size_t)2 * CC * CC];
__device__ __half h_Wp[(size_t)CC * CC];
__device__ __half h_Q [(size_t)NB * CC * NN];
__device__ __half h_KV[(size_t)NB * 2 * CC * TP];
__device__ __half h_P [(size_t)NB * NH * NN * TP];
__device__ __half h_O [(size_t)NB * CC * NN];

__device__ __forceinline__ uint32_t smem_u32(const void* p) {
    uint32_t a;
    asm("{ .reg .u64 t; cvta.to.shared.u64 t, %1; cvt.u32.u64 %0, t; }" : "=r"(a) : "l"(p));
    return a;
}
#define CP16(d, s, sz) asm volatile("cp.async.cg.shared.global [%0], [%1], 16, %2;" :: "r"(d), "l"(s), "r"(sz) : "memory")
#define CP_COMMIT()    asm volatile("cp.async.commit_group;" ::: "memory")
#define CP_WAIT1()     asm volatile("cp.async.wait_group 1;" ::: "memory")

#define LDSM_X4(r0, r1, r2, r3, a) \
    asm volatile("ldmatrix.sync.aligned.m8n8.x4.shared.b16 {%0,%1,%2,%3}, [%4];" \
        : "=r"(r0), "=r"(r1), "=r"(r2), "=r"(r3) : "r"(a))
#define LDSM_X4T(r0, r1, r2, r3, a) \
    asm volatile("ldmatrix.sync.aligned.m8n8.x4.trans.shared.b16 {%0,%1,%2,%3}, [%4];" \
        : "=r"(r0), "=r"(r1), "=r"(r2), "=r"(r3) : "r"(a))

__device__ __forceinline__ void mma_f16(float* c, const uint32_t* a, const uint32_t* b) {
    asm volatile(
        "mma.sync.aligned.m16n8k16.row.col.f32.f16.f16.f32 "
        "{%0,%1,%2,%3}, {%4,%5,%6,%7}, {%8,%9}, {%0,%1,%2,%3};\n"
        : "+f"(c[0]), "+f"(c[1]), "+f"(c[2]), "+f"(c[3])
        : "r"(a[0]), "r"(a[1]), "r"(a[2]), "r"(a[3]), "r"(b[0]), "r"(b[1]));
}

// ---------------------------------------------------------------------------
// Generic fp16 GEMM, 128x128x32 tiles, 8 warps (4m x 2n), warp tile 32x64.
//   AT=0: A[m][k] k-contig (row-major), smem [m][40]h,  ldmatrix normal.
//   AT=1: A[k][m] m-contig (col-major), smem [k][136]h, ldmatrix.trans.
//   BT=1: B[k][n] n-contig,             smem [k][136]h, ldmatrix.trans.
//   BT=0: B[n][k] k-contig,             smem [n][40]h,  ldmatrix normal.
//   OM: 0 = fp32 out + bias; 1 = fp16 out + bias (cols>=nvalid forced 0);
//       2 = softmax over cols [0,77) then fp16 out (ldc=80).
// sA: stride of A's non-contiguous dim; sB likewise. Ka/Bb: contig-dim read
// bounds for cp.async zero-fill. M % 128 == 0.
// ---------------------------------------------------------------------------
#define STAGE_B 20480

template <bool AT, bool BT, int OM>
__global__ __launch_bounds__(256, 2)
void hgemm(const __half* __restrict__ A, const __half* __restrict__ B,
           void* __restrict__ Cv, const float* __restrict__ bias,
           int M, int N, int K,
           long long sA, long long sB, long long ldc,
           long long sAb, long long sAh, long long sBb, long long sBh,
           long long sCb, long long sCh, int nh, float alpha,
           int Ka, int Bbound, int nvalid)
{
    extern __shared__ char smem[];
    const uint32_t sb = smem_u32(smem);

    const int tid  = threadIdx.x;
    const int lane = tid & 31;
    const int warp = tid >> 5;
    const int wm = (warp & 3) * 32;
    const int wn = (warp >> 2) * 64;
    const int gid = lane >> 2;
    const int tig = lane & 3;
    const int tl  = lane >> 3;       // ldmatrix tile id 0..3
    const int rr  = lane & 7;        // row within tile

    const int z = blockIdx.z;
    const int b = z / nh;
    const int h = z - b * nh;
    const __half* Ab = A + (size_t)b * sAb + (size_t)h * sAh;
    const __half* Bb = B + (size_t)b * sBb + (size_t)h * sBh;

    const int m0 = blockIdx.y * 128;
    const int n0 = blockIdx.x * 128;
    const int nkt = (K + 31) >> 5;

    auto load_tile = [&](int kt, int s) {
        const int k0 = kt << 5;
        const uint32_t aB = sb + (uint32_t)s * STAGE_B;
        const uint32_t bB = aB + 10240;
        #pragma unroll
        for (int i = 0; i < 2; i++) {
            int sg = tid + i * 256;
            if (!AT) {
                int m = sg >> 2, sk = sg & 3;
                const __half* src = Ab + (size_t)(m0 + m) * sA + k0 + sk * 8;
                CP16(aB + (uint32_t)(m * 40 + sk * 8) * 2, src,
                     (k0 + sk * 8 < Ka) ? 16 : 0);
            } else {
                int k = sg >> 4, sm = sg & 15;
                const __half* src = Ab + (size_t)(k0 + k) * sA + m0 + sm * 8;
                CP16(aB + (uint32_t)(k * 136 + sm * 8) * 2, src, 16);
            }
        }
        #pragma unroll
        for (int i = 0; i < 2; i++) {
            int sg = tid + i * 256;
            if (BT) {
                int k = sg >> 4, sn = sg & 15;
                const __half* src = Bb + (size_t)(k0 + k) * sB + n0 + sn * 8;
                CP16(bB + (uint32_t)(k * 136 + sn * 8) * 2, src,
                     (n0 + sn * 8 < Bbound) ? 16 : 0);
            } else {
                int n = sg >> 2, sk = sg & 3;
                const __half* src = Bb + (size_t)(n0 + n) * sB + k0 + sk * 8;
                CP16(bB + (uint32_t)(n * 40 + sk * 8) * 2, src,
                     (k0 + sk * 8 < Bbound) ? 16 : 0);
            }
        }
        CP_COMMIT();
    };

    float acc[2][8][4];
    #pragma unroll
    for (int mi = 0; mi < 2; mi++)
        #pragma unroll
        for (int ni = 0; ni < 8; ni++)
            #pragma unroll
            for (int j = 0; j < 4; j++) acc[mi][ni][j] = 0.f;

    load_tile(0, 0);
    if (nkt > 1) load_tile(1, 1); else CP_COMMIT();

    for (int kt = 0; kt < nkt; kt++) {
        CP_WAIT1();
        __syncthreads();
        if (kt + 2 < nkt) load_tile(kt + 2, (kt + 2) % 3);
        else CP_COMMIT();

        const uint32_t aB = sb + (uint32_t)((kt % 3) * STAGE_B);
        const uint32_t bB = aB + 10240;

        #pragma unroll
        for (int kk = 0; kk < 32; kk += 16) {
            uint32_t afr[2][4], bfr[8][2];
            #pragma unroll
            for (int mi = 0; mi < 2; mi++) {
                uint32_t addr;
                if (!AT)
                    addr = aB + (uint32_t)((wm + mi * 16 + (tl & 1) * 8 + rr) * 40
                                           + kk + (tl >> 1) * 8) * 2;
                else
                    addr = aB + (uint32_t)((kk + (tl >> 1) * 8 + rr) * 136
                                           + wm + mi * 16 + (tl & 1) * 8) * 2;
                if (!AT) LDSM_X4 (afr[mi][0], afr[mi][1], afr[mi][2], afr[mi][3], addr);
                else     LDSM_X4T(afr[mi][0], afr[mi][1], afr[mi][2], afr[mi][3], addr);
            }
            #pragma unroll
            for (int np = 0; np < 4; np++) {
                int nb = wn + np * 16;
                uint32_t addr;
                if (BT)
                    addr = bB + (uint32_t)((kk + (tl & 1) * 8 + rr) * 136
                                           + nb + (tl >> 1) * 8) * 2;
                else
                    addr = bB + (uint32_t)((nb + (tl >> 1) * 8 + rr) * 40
                                           + kk + (tl & 1) * 8) * 2;
                if (BT) LDSM_X4T(bfr[2*np][0], bfr[2*np][1], bfr[2*np+1][0], bfr[2*np+1][1], addr);
                else    LDSM_X4 (bfr[2*np][0], bfr[2*np][1], bfr[2*np+1][0], bfr[2*np+1][1], addr);
            }
            #pragma unroll
            for (int mi = 0; mi < 2; mi++)
                #pragma unroll
                for (int ni = 0; ni < 8; ni++)
                    mma_f16(acc[mi][ni], afr[mi], bfr[ni]);
        }
    }

    // ------------------------------------------------------------ epilogues
    if (OM == 0) {
        float* Cb = (float*)Cv + (size_t)b * sCb + (size_t)h * sCh;
        #pragma unroll
        for (int mi = 0; mi < 2; mi++) {
            int r0 = m0 + wm + mi * 16 + gid;
            float bv0 = bias ? bias[r0]     : 0.f;
            float bv1 = bias ? bias[r0 + 8] : 0.f;
            #pragma unroll
            for (int ni = 0; ni < 8; ni++) {
                int c0 = n0 + wn + ni * 8 + 2 * tig;
                if (c0 < N) {
                    Cb[(size_t)r0 * ldc + c0]       = alpha * acc[mi][ni][0] + bv0;
                    Cb[(size_t)(r0 + 8) * ldc + c0] = alpha * acc[mi][ni][2] + bv1;
                    Cb[(size_t)r0 * ldc + c0 + 1]       = alpha * acc[mi][ni][1] + bv0;
                    Cb[(size_t)(r0 + 8) * ldc + c0 + 1] = alpha * acc[mi][ni][3] + bv1;
                }
            }
        }
    } else if (OM == 1) {
        __half* Cb = (__half*)Cv + (size_t)b * sCb + (size_t)h * sCh;
        #pragma unroll
        for (int mi = 0; mi < 2; mi++) {
            int r0 = m0 + wm + mi * 16 + gid;
            float bv0 = bias ? bias[r0]     : 0.f;
            float bv1 = bias ? bias[r0 + 8] : 0.f;
            #pragma unroll
            for (int ni = 0; ni < 8; ni++) {
                int c0 = n0 + wn + ni * 8 + 2 * tig;
                if (c0 < N) {
                    #pragma unroll
                    for (int j = 0; j < 2; j++) {
                        int c = c0 + j;
                        bool v = (c < nvalid);
                        Cb[(size_t)r0 * ldc + c] =
                            __float2half(v ? alpha * acc[mi][ni][j] + bv0 : 0.f);
                        Cb[(size_t)(r0 + 8) * ldc + c] =
                            __float2half(v ? alpha * acc[mi][ni][2 + j] + bv1 : 0.f);
                    }
                }
            }
        }
    } else {
        // OM==2: softmax over cols [0,77), output fp16 row pitch 80.
        __half* Cb = (__half*)Cv + (size_t)b * sCb + (size_t)h * sCh;
        float* st = (float*)smem;                       // [128][84]
        __syncthreads();                                 // mainloop smem reads done
        #pragma unroll
        for (int mi = 0; mi < 2; mi++) {
            int rl = wm + mi * 16 + gid;
            #pragma unroll
            for (int ni = 0; ni < 8; ni++) {
                int c0 = wn + ni * 8 + 2 * tig;
                if (c0 < TP) {
                    st[rl * 84 + c0]            = alpha * acc[mi][ni][0];
                    st[rl * 84 + c0 + 1]        = alpha * acc[mi][ni][1];
                    st[(rl + 8) * 84 + c0]      = alpha * acc[mi][ni][2];
                    st[(rl + 8) * 84 + c0 + 1]  = alpha * acc[mi][ni][3];
                }
            }
        }
        __syncthreads();
        for (int i = 0; i < 16; i++) {
            int rl = warp * 16 + i;
            float* row = st + rl * 84;
            float x0 = row[lane];
            float x1 = row[lane + 32];
            float x2 = (lane + 64 < TT) ? row[lane + 64] : -1e30f;
            float m = fmaxf(x0, fmaxf(x1, x2));
            #pragma unroll
            for (int off = 16; off > 0; off >>= 1)
                m = fmaxf(m, __shfl_xor_sync(0xFFFFFFFFu, m, off));
            float e0 = __expf(x0 - m);
            float e1 = __expf(x1 - m);
            float e2 = (lane + 64 < TT) ? __expf(x2 - m) : 0.f;
            float s = e0 + e1 + e2;
            #pragma unroll
            for (int off = 16; off > 0; off >>= 1)
                s += __shfl_xor_sync(0xFFFFFFFFu, s, off);
            float inv = 1.f / s;
            __half* dst = Cb + (size_t)(m0 + rl) * TP;
            dst[lane]      = __float2half(e0 * inv);
            dst[lane + 32] = __float2half(e1 * inv);
            if (lane + 64 < TP)
                dst[lane + 64] = __float2half((lane + 64 < TT) ? e2 * inv : 0.f);
        }
    }
}

// ---------------------------------------------------------------- converters
__global__ void f2h4(const float* __restrict__ s, __half* __restrict__ d, int n4)
{
    int i = blockIdx.x * 256 + threadIdx.x;
    if (i < n4) {
        float4 v = reinterpret_cast<const float4*>(s)[i];
        __half2* d2 = reinterpret_cast<__half2*>(d);
        d2[2 * i]     = __floats2half2_rn(v.x, v.y);
        d2[2 * i + 1] = __floats2half2_rn(v.z, v.w);
    }
}
__global__ void f2h_pad77(const float* __restrict__ s, __half* __restrict__ d, int rows)
{
    int r = blockIdx.x, c = threadIdx.x;
    if (c < TP)
        d[(size_t)r * TP + c] = __float2half((c < TT) ? s[(size_t)r * TT + c] : 0.f);
}

// ---------------------------------------------------------------- launch
extern "C" void kernel_launch(void* const* d_in, const int* in_sizes, int n_in,
                              void* d_out, int out_size)
{
    const float* Vx  = (const float*)d_in[0];
    const float* Tx  = (const float*)d_in[1];
    const float* Wq  = (const float*)d_in[2];
    const float* bq  = (const float*)d_in[3];
    const float* Wkv = (const float*)d_in[4];
    const float* bkv = (const float*)d_in[5];
    const float* Wp  = (const float*)d_in[6];
    const float* bp  = (const float*)d_in[7];
    float* Y = (float*)d_out;

    __half *hVx, *hTx, *hWq, *hWkv, *hWp, *hQ, *hKV, *hP, *hO;
    cudaGetSymbolAddress((void**)&hVx, h_Vx);
    cudaGetSymbolAddress((void**)&hTx, h_Tx);
    cudaGetSymbolAddress((void**)&hWq, h_Wq);
    cudaGetSymbolAddress((void**)&hWkv, h_Wkv);
    cudaGetSymbolAddress((void**)&hWp, h_Wp);
    cudaGetSymbolAddress((void**)&hQ,  h_Q);
    cudaGetSymbolAddress((void**)&hKV, h_KV);
    cudaGetSymbolAddress((void**)&hP,  h_P);
    cudaGetSymbolAddress((void**)&hO,  h_O);

    constexpr int SMEM_BYTES = STAGE_B * 3;   // 61440
    cudaFuncSetAttribute(hgemm<false, true, 1>, cudaFuncAttributeMaxDynamicSharedMemorySize, SMEM_BYTES);
    cudaFuncSetAttribute(hgemm<true,  true, 2>, cudaFuncAttributeMaxDynamicSharedMemorySize, SMEM_BYTES);
    cudaFuncSetAttribute(hgemm<false, false,1>, cudaFuncAttributeMaxDynamicSharedMemorySize, SMEM_BYTES);
    cudaFuncSetAttribute(hgemm<false, true, 0>, cudaFuncAttributeMaxDynamicSharedMemorySize, SMEM_BYTES);

    const float scale = 0.08838834764831843f;  // 1/sqrt(128)

    // 0) fp32 -> fp16 scratch
    f2h4<<<(NB * CC * NN / 4 + 255) / 256, 256>>>(Vx, hVx, NB * CC * NN / 4);
    f2h4<<<(CC * CC / 4 + 255) / 256, 256>>>(Wq, hWq, CC * CC / 4);
    f2h4<<<(2 * CC * CC / 4 + 255) / 256, 256>>>(Wkv, hWkv, 2 * CC * CC / 4);
    f2h4<<<(CC * CC / 4 + 255) / 256, 256>>>(Wp, hWp, CC * CC / 4);
    f2h_pad77<<<NB * CC, 128>>>(Tx, hTx, NB * CC);

    // 1) KV = Wkv @ Tx + bkv : M=2048, N=80(valid 77), K=1024, per-b
    hgemm<false, true, 1><<<dim3(1, 16, NB), 256, SMEM_BYTES>>>(
        hWkv, hTx, hKV, bkv, 2048, TP, CC,
        CC, TP, TP,
        0, 0, (long long)CC * TP, 0,
        (long long)2 * CC * TP, 0, 1, 1.0f, CC, TP, TT);

    // 2) Q = Wq @ Vx + bq : M=1024, N=1024, K=1024, per-b
    hgemm<false, true, 1><<<dim3(8, 8, NB), 256, SMEM_BYTES>>>(
        hWq, hVx, hQ, bq, CC, NN, CC,
        CC, NN, NN,
        0, 0, (long long)CC * NN, 0,
        (long long)CC * NN, 0, 1, 1.0f, CC, NN, NN);

    // 3) P = softmax(scale * Q_h^T K_h) : M=1024(n), N=77(t), K=128, per-(b,h)
    hgemm<true, true, 2><<<dim3(1, 8, NB * NH), 256, SMEM_BYTES>>>(
        hQ, hKV, hP, nullptr, NN, TT, HD,
        NN, TP, TP,
        (long long)CC * NN, (long long)HD * NN,
        (long long)2 * CC * TP, (long long)2 * HD * TP,
        (long long)NH * NN * TP, (long long)NN * TP,
        NH, scale, HD, TP, TT);

    // 4) O = V_h @ P^T : M=128(d), N=1024(n), K=77, per-(b,h)
    hgemm<false, false, 1><<<dim3(8, 1, NB * NH), 256, SMEM_BYTES>>>(
        hKV + (size_t)HD * TP, hP, hO, nullptr, HD, NN, TT,
        TP, TP, NN,
        (long long)2 * CC * TP, (long long)2 * HD * TP,
        (long long)NH * NN * TP, (long long)NN * TP,
        (long long)CC * NN, (long long)HD * NN,
        NH, 1.0f, TP, TP, NN);

    // 5) Y = Wp @ O + bp : M=1024, N=1024, K=1024, per-b, fp32 out
    hgemm<false, true, 0><<<dim3(8, 8, NB), 256, SMEM_BYTES>>>(
        hWp, hO, Y, bp, CC, NN, CC,
        CC, NN, NN,
        0, 0, (long long)CC * NN, 0,
        (long long)CC * NN, 0, 1, 1.0f, CC, NN, NN);
}

// round 8
// speedup vs baseline: 2.7313x; 1.3335x over previous
#include <cuda_runtime.h>
#include <cuda_fp16.h>
#include <cstdint>

// ---------------------------------------------------------------------------
// B=16, C=1024, N=1024, T=77(pad 80), heads=8, hd=128.  All GEMMs fp16
// mma.sync.m16n8k16 (fp32 accum) + ldmatrix + 3-stage cp.async.
//   big GEMMs (Q, Y): 256x128x32 tiles, 512 thr  (L2-traffic optimized)
//   small GEMMs (KV, S+softmax, O): 128x128x32 tiles, 256 thr
// Softmax fused into S-GEMM epilogue. Scratch fp16; cols 77..79 stored zero.
// KV head split: K_h rows [256h,256h+128), V_h rows [256h+128,256h+256).
// ---------------------------------------------------------------------------

#define NB 16
#define CC 1024
#define NN 1024
#define TT 77
#define TP 80
#define NH 8
#define HD 128

__device__ __half h_Vx[(size_t)NB * CC * NN];
__device__ __half h_Tx[(size_t)NB * CC * TP];
__device__ __half h_Wq[(size_t)CC * CC];
__device__ __half h_Wkv[(size_t)2 * CC * CC];
__device__ __half h_Wp[(size_t)CC * CC];
__device__ __half h_Q [(size_t)NB * CC * NN];
__device__ __half h_KV[(size_t)NB * 2 * CC * TP];
__device__ __half h_P [(size_t)NB * NH * NN * TP];
__device__ __half h_O [(size_t)NB * CC * NN];

__device__ __forceinline__ uint32_t smem_u32(const void* p) {
    uint32_t a;
    asm("{ .reg .u64 t; cvta.to.shared.u64 t, %1; cvt.u32.u64 %0, t; }" : "=r"(a) : "l"(p));
    return a;
}
#define CP16(d, s, sz) asm volatile("cp.async.cg.shared.global [%0], [%1], 16, %2;" :: "r"(d), "l"(s), "r"(sz) : "memory")
#define CP_COMMIT()    asm volatile("cp.async.commit_group;" ::: "memory")
#define CP_WAIT1()     asm volatile("cp.async.wait_group 1;" ::: "memory")

#define LDSM_X4(r0, r1, r2, r3, a) \
    asm volatile("ldmatrix.sync.aligned.m8n8.x4.shared.b16 {%0,%1,%2,%3}, [%4];" \
        : "=r"(r0), "=r"(r1), "=r"(r2), "=r"(r3) : "r"(a))
#define LDSM_X4T(r0, r1, r2, r3, a) \
    asm volatile("ldmatrix.sync.aligned.m8n8.x4.trans.shared.b16 {%0,%1,%2,%3}, [%4];" \
        : "=r"(r0), "=r"(r1), "=r"(r2), "=r"(r3) : "r"(a))

__device__ __forceinline__ void mma_f16(float* c, const uint32_t* a, const uint32_t* b) {
    asm volatile(
        "mma.sync.aligned.m16n8k16.row.col.f32.f16.f16.f32 "
        "{%0,%1,%2,%3}, {%4,%5,%6,%7}, {%8,%9}, {%0,%1,%2,%3};\n"
        : "+f"(c[0]), "+f"(c[1]), "+f"(c[2]), "+f"(c[3])
        : "r"(a[0]), "r"(a[1]), "r"(a[2]), "r"(a[3]), "r"(b[0]), "r"(b[1]));
}

// ===========================================================================
// BIG GEMM: C[z][m,n] = A[m,:]@B[z][:,n] + bias[m].  M=1024(4 blk of 256),
// N=1024(8 blk of 128), K=1024.  A: weights [M][K] row-major (k-contig).
// B: [K][N] n-contig per batch.  No tails.  OM: 0=fp32 out, 1=fp16 out.
// 512 threads: 16 warps = 4m x 4n, warp tile 64x32.
// ===========================================================================
#define BIG_A_B 20480                      // 256*40*2
#define BIG_B_B 8704                       // 32*136*2
#define BIG_STAGE (BIG_A_B + BIG_B_B)      // 29184
#define BIG_SMEM (BIG_STAGE * 3)           // 87552

template <int OM>
__global__ __launch_bounds__(512, 1)
void hgemm_big(const __half* __restrict__ A, const __half* __restrict__ B,
               void* __restrict__ Cv, const float* __restrict__ bias,
               long long sBb, long long sCb)
{
    extern __shared__ char smem[];
    const uint32_t sb = smem_u32(smem);

    const int tid  = threadIdx.x;
    const int lane = tid & 31;
    const int warp = tid >> 5;
    const int wm = (warp & 3) * 64;
    const int wn = (warp >> 2) * 32;
    const int gid = lane >> 2;
    const int tig = lane & 3;
    const int tl  = lane >> 3;
    const int rr  = lane & 7;

    const int m0 = blockIdx.y * 256;
    const int n0 = blockIdx.x * 128;
    const __half* Bb = B + (size_t)blockIdx.z * sBb;

    auto load_tile = [&](int kt, int s) {
        const int k0 = kt << 5;
        const uint32_t aB = sb + (uint32_t)s * BIG_STAGE;
        const uint32_t bB = aB + BIG_A_B;
        #pragma unroll
        for (int i = 0; i < 2; i++) {                    // A: 256m x 32k
            int sg = tid + i * 512;
            int m = sg >> 2, sk = sg & 3;
            CP16(aB + (uint32_t)(m * 40 + sk * 8) * 2,
                 A + (size_t)(m0 + m) * CC + k0 + sk * 8, 16);
        }
        {                                                // B: 32k x 128n
            int k = tid >> 4, sn = tid & 15;
            CP16(bB + (uint32_t)(k * 136 + sn * 8) * 2,
                 Bb + (size_t)(k0 + k) * NN + n0 + sn * 8, 16);
        }
        CP_COMMIT();
    };

    float acc[4][4][4];
    #pragma unroll
    for (int mi = 0; mi < 4; mi++)
        #pragma unroll
        for (int ni = 0; ni < 4; ni++)
            #pragma unroll
            for (int j = 0; j < 4; j++) acc[mi][ni][j] = 0.f;

    load_tile(0, 0);
    load_tile(1, 1);

    const int nkt = CC >> 5;
    for (int kt = 0; kt < nkt; kt++) {
        CP_WAIT1();
        __syncthreads();
        if (kt + 2 < nkt) load_tile(kt + 2, (kt + 2) % 3);
        else CP_COMMIT();

        const uint32_t aB = sb + (uint32_t)((kt % 3) * BIG_STAGE);
        const uint32_t bB = aB + BIG_A_B;

        #pragma unroll
        for (int kk = 0; kk < 32; kk += 16) {
            uint32_t afr[4][4], bfr[4][2];
            #pragma unroll
            for (int mi = 0; mi < 4; mi++) {
                uint32_t addr = aB + (uint32_t)((wm + mi * 16 + (tl & 1) * 8 + rr) * 40
                                                + kk + (tl >> 1) * 8) * 2;
                LDSM_X4(afr[mi][0], afr[mi][1], afr[mi][2], afr[mi][3], addr);
            }
            #pragma unroll
            for (int np = 0; np < 2; np++) {
                uint32_t addr = bB + (uint32_t)((kk + (tl & 1) * 8 + rr) * 136
                                                + wn + np * 16 + (tl >> 1) * 8) * 2;
                LDSM_X4T(bfr[2*np][0], bfr[2*np][1], bfr[2*np+1][0], bfr[2*np+1][1], addr);
            }
            #pragma unroll
            for (int mi = 0; mi < 4; mi++)
                #pragma unroll
                for (int ni = 0; ni < 4; ni++)
                    mma_f16(acc[mi][ni], afr[mi], bfr[ni]);
        }
    }

    #pragma unroll
    for (int mi = 0; mi < 4; mi++) {
        int r0 = m0 + wm + mi * 16 + gid;
        float bv0 = bias[r0];
        float bv1 = bias[r0 + 8];
        #pragma unroll
        for (int ni = 0; ni < 4; ni++) {
            int c0 = n0 + wn + ni * 8 + 2 * tig;
            if (OM == 0) {
                float* Cb = (float*)Cv + (size_t)blockIdx.z * sCb;
                Cb[(size_t)r0 * NN + c0]           = acc[mi][ni][0] + bv0;
                Cb[(size_t)r0 * NN + c0 + 1]       = acc[mi][ni][1] + bv0;
                Cb[(size_t)(r0 + 8) * NN + c0]     = acc[mi][ni][2] + bv1;
                Cb[(size_t)(r0 + 8) * NN + c0 + 1] = acc[mi][ni][3] + bv1;
            } else {
                __half* Cb = (__half*)Cv + (size_t)blockIdx.z * sCb;
                Cb[(size_t)r0 * NN + c0]           = __float2half(acc[mi][ni][0] + bv0);
                Cb[(size_t)r0 * NN + c0 + 1]       = __float2half(acc[mi][ni][1] + bv0);
                Cb[(size_t)(r0 + 8) * NN + c0]     = __float2half(acc[mi][ni][2] + bv1);
                Cb[(size_t)(r0 + 8) * NN + c0 + 1] = __float2half(acc[mi][ni][3] + bv1);
            }
        }
    }
}

// ===========================================================================
// Small generic GEMM (KV, S+softmax, O) — as round 7.
//   AT=0: A[m][k] k-contig, smem [m][40]h;  AT=1: A[k][m] m-contig, [k][136]h.
//   BT=1: B[k][n] n-contig, [k][136]h;      BT=0: B[n][k] k-contig, [n][40]h.
//   OM: 1 = fp16 out + bias (cols>=nvalid forced 0); 2 = fused softmax.
// ===========================================================================
#define STAGE_B 20480

template <bool AT, bool BT, int OM>
__global__ __launch_bounds__(256, 2)
void hgemm(const __half* __restrict__ A, const __half* __restrict__ B,
           void* __restrict__ Cv, const float* __restrict__ bias,
           int M, int N, int K,
           long long sA, long long sB, long long ldc,
           long long sAb, long long sAh, long long sBb, long long sBh,
           long long sCb, long long sCh, int nh, float alpha,
           int Ka, int Bbound, int nvalid)
{
    extern __shared__ char smem[];
    const uint32_t sb = smem_u32(smem);

    const int tid  = threadIdx.x;
    const int lane = tid & 31;
    const int warp = tid >> 5;
    const int wm = (warp & 3) * 32;
    const int wn = (warp >> 2) * 64;
    const int gid = lane >> 2;
    const int tig = lane & 3;
    const int tl  = lane >> 3;
    const int rr  = lane & 7;

    const int z = blockIdx.z;
    const int b = z / nh;
    const int h = z - b * nh;
    const __half* Ab = A + (size_t)b * sAb + (size_t)h * sAh;
    const __half* Bb = B + (size_t)b * sBb + (size_t)h * sBh;

    const int m0 = blockIdx.y * 128;
    const int n0 = blockIdx.x * 128;
    const int nkt = (K + 31) >> 5;

    auto load_tile = [&](int kt, int s) {
        const int k0 = kt << 5;
        const uint32_t aB = sb + (uint32_t)s * STAGE_B;
        const uint32_t bB = aB + 10240;
        #pragma unroll
        for (int i = 0; i < 2; i++) {
            int sg = tid + i * 256;
            if (!AT) {
                int m = sg >> 2, sk = sg & 3;
                CP16(aB + (uint32_t)(m * 40 + sk * 8) * 2,
                     Ab + (size_t)(m0 + m) * sA + k0 + sk * 8,
                     (k0 + sk * 8 < Ka) ? 16 : 0);
            } else {
                int k = sg >> 4, sm = sg & 15;
                CP16(aB + (uint32_t)(k * 136 + sm * 8) * 2,
                     Ab + (size_t)(k0 + k) * sA + m0 + sm * 8, 16);
            }
        }
        #pragma unroll
        for (int i = 0; i < 2; i++) {
            int sg = tid + i * 256;
            if (BT) {
                int k = sg >> 4, sn = sg & 15;
                CP16(bB + (uint32_t)(k * 136 + sn * 8) * 2,
                     Bb + (size_t)(k0 + k) * sB + n0 + sn * 8,
                     (n0 + sn * 8 < Bbound) ? 16 : 0);
            } else {
                int n = sg >> 2, sk = sg & 3;
                CP16(bB + (uint32_t)(n * 40 + sk * 8) * 2,
                     Bb + (size_t)(n0 + n) * sB + k0 + sk * 8,
                     (k0 + sk * 8 < Bbound) ? 16 : 0);
            }
        }
        CP_COMMIT();
    };

    float acc[2][8][4];
    #pragma unroll
    for (int mi = 0; mi < 2; mi++)
        #pragma unroll
        for (int ni = 0; ni < 8; ni++)
            #pragma unroll
            for (int j = 0; j < 4; j++) acc[mi][ni][j] = 0.f;

    load_tile(0, 0);
    if (nkt > 1) load_tile(1, 1); else CP_COMMIT();

    for (int kt = 0; kt < nkt; kt++) {
        CP_WAIT1();
        __syncthreads();
        if (kt + 2 < nkt) load_tile(kt + 2, (kt + 2) % 3);
        else CP_COMMIT();

        const uint32_t aB = sb + (uint32_t)((kt % 3) * STAGE_B);
        const uint32_t bB = aB + 10240;

        #pragma unroll
        for (int kk = 0; kk < 32; kk += 16) {
            uint32_t afr[2][4], bfr[8][2];
            #pragma unroll
            for (int mi = 0; mi < 2; mi++) {
                uint32_t addr;
                if (!AT)
                    addr = aB + (uint32_t)((wm + mi * 16 + (tl & 1) * 8 + rr) * 40
                                           + kk + (tl >> 1) * 8) * 2;
                else
                    addr = aB + (uint32_t)((kk + (tl >> 1) * 8 + rr) * 136
                                           + wm + mi * 16 + (tl & 1) * 8) * 2;
                if (!AT) LDSM_X4 (afr[mi][0], afr[mi][1], afr[mi][2], afr[mi][3], addr);
                else     LDSM_X4T(afr[mi][0], afr[mi][1], afr[mi][2], afr[mi][3], addr);
            }
            #pragma unroll
            for (int np = 0; np < 4; np++) {
                int nb = wn + np * 16;
                uint32_t addr;
                if (BT)
                    addr = bB + (uint32_t)((kk + (tl & 1) * 8 + rr) * 136
                                           + nb + (tl >> 1) * 8) * 2;
                else
                    addr = bB + (uint32_t)((nb + (tl >> 1) * 8 + rr) * 40
                                           + kk + (tl & 1) * 8) * 2;
                if (BT) LDSM_X4T(bfr[2*np][0], bfr[2*np][1], bfr[2*np+1][0], bfr[2*np+1][1], addr);
                else    LDSM_X4 (bfr[2*np][0], bfr[2*np][1], bfr[2*np+1][0], bfr[2*np+1][1], addr);
            }
            #pragma unroll
            for (int mi = 0; mi < 2; mi++)
                #pragma unroll
                for (int ni = 0; ni < 8; ni++)
                    mma_f16(acc[mi][ni], afr[mi], bfr[ni]);
        }
    }

    if (OM == 1) {
        __half* Cb = (__half*)Cv + (size_t)b * sCb + (size_t)h * sCh;
        #pragma unroll
        for (int mi = 0; mi < 2; mi++) {
            int r0 = m0 + wm + mi * 16 + gid;
            float bv0 = bias ? bias[r0]     : 0.f;
            float bv1 = bias ? bias[r0 + 8] : 0.f;
            #pragma unroll
            for (int ni = 0; ni < 8; ni++) {
                int c0 = n0 + wn + ni * 8 + 2 * tig;
                if (c0 < N) {
                    #pragma unroll
                    for (int j = 0; j < 2; j++) {
                        int c = c0 + j;
                        bool v = (c < nvalid);
                        Cb[(size_t)r0 * ldc + c] =
                            __float2half(v ? alpha * acc[mi][ni][j] + bv0 : 0.f);
                        Cb[(size_t)(r0 + 8) * ldc + c] =
                            __float2half(v ? alpha * acc[mi][ni][2 + j] + bv1 : 0.f);
                    }
                }
            }
        }
    } else {
        // OM==2: softmax over cols [0,77), fp16 out, row pitch 80.
        __half* Cb = (__half*)Cv + (size_t)b * sCb + (size_t)h * sCh;
        float* st = (float*)smem;                        // [128][84]
        __syncthreads();
        #pragma unroll
        for (int mi = 0; mi < 2; mi++) {
            int rl = wm + mi * 16 + gid;
            #pragma unroll
            for (int ni = 0; ni < 8; ni++) {
                int c0 = wn + ni * 8 + 2 * tig;
                if (c0 < TP) {
                    st[rl * 84 + c0]            = alpha * acc[mi][ni][0];
                    st[rl * 84 + c0 + 1]        = alpha * acc[mi][ni][1];
                    st[(rl + 8) * 84 + c0]      = alpha * acc[mi][ni][2];
                    st[(rl + 8) * 84 + c0 + 1]  = alpha * acc[mi][ni][3];
                }
            }
        }
        __syncthreads();
        for (int i = 0; i < 16; i++) {
            int rl = warp * 16 + i;
            float* row = st + rl * 84;
            float x0 = row[lane];
            float x1 = row[lane + 32];
            float x2 = (lane + 64 < TT) ? row[lane + 64] : -1e30f;
            float m = fmaxf(x0, fmaxf(x1, x2));
            #pragma unroll
            for (int off = 16; off > 0; off >>= 1)
                m = fmaxf(m, __shfl_xor_sync(0xFFFFFFFFu, m, off));
            float e0 = __expf(x0 - m);
            float e1 = __expf(x1 - m);
            float e2 = (lane + 64 < TT) ? __expf(x2 - m) : 0.f;
            float s = e0 + e1 + e2;
            #pragma unroll
            for (int off = 16; off > 0; off >>= 1)
                s += __shfl_xor_sync(0xFFFFFFFFu, s, off);
            float inv = 1.f / s;
            __half* dst = Cb + (size_t)(m0 + rl) * TP;
            dst[lane]      = __float2half(e0 * inv);
            dst[lane + 32] = __float2half(e1 * inv);
            if (lane + 64 < TP)
                dst[lane + 64] = __float2half((lane + 64 < TT) ? e2 * inv : 0.f);
        }
    }
}

// ---------------------------------------------------------------- converters
#define N4_VX  (NB * CC * NN / 4)
#define N4_WQ  (CC * CC / 4)
#define N4_WKV (2 * CC * CC / 4)

__global__ void f2h_all(const float* __restrict__ Vx, const float* __restrict__ Wq,
                        const float* __restrict__ Wkv, const float* __restrict__ Wp,
                        __half* __restrict__ dVx, __half* __restrict__ dWq,
                        __half* __restrict__ dWkv, __half* __restrict__ dWp)
{
    int i = blockIdx.x * 256 + threadIdx.x;
    const float* s; __half* d; int j;
    if (i < N4_VX)                       { s = Vx;  d = dVx;  j = i; }
    else if (i < N4_VX + N4_WQ)          { s = Wq;  d = dWq;  j = i - N4_VX; }
    else if (i < N4_VX + N4_WQ + N4_WKV) { s = Wkv; d = dWkv; j = i - N4_VX - N4_WQ; }
    else                                 { s = Wp;  d = dWp;  j = i - N4_VX - N4_WQ - N4_WKV; }
    float4 v = reinterpret_cast<const float4*>(s)[j];
    __half2* d2 = reinterpret_cast<__half2*>(d);
    d2[2 * j]     = __floats2half2_rn(v.x, v.y);
    d2[2 * j + 1] = __floats2half2_rn(v.z, v.w);
}
__global__ void f2h_pad77(const float* __restrict__ s, __half* __restrict__ d, int rows)
{
    int r = blockIdx.x, c = threadIdx.x;
    if (c < TP)
        d[(size_t)r * TP + c] = __float2half((c < TT) ? s[(size_t)r * TT + c] : 0.f);
}

// ---------------------------------------------------------------- launch
extern "C" void kernel_launch(void* const* d_in, const int* in_sizes, int n_in,
                              void* d_out, int out_size)
{
    const float* Vx  = (const float*)d_in[0];
    const float* Tx  = (const float*)d_in[1];
    const float* Wq  = (const float*)d_in[2];
    const float* bq  = (const float*)d_in[3];
    const float* Wkv = (const float*)d_in[4];
    const float* bkv = (const float*)d_in[5];
    const float* Wp  = (const float*)d_in[6];
    const float* bp  = (const float*)d_in[7];
    float* Y = (float*)d_out;

    __half *hVx, *hTx, *hWq, *hWkv, *hWp, *hQ, *hKV, *hP, *hO;
    cudaGetSymbolAddress((void**)&hVx, h_Vx);
    cudaGetSymbolAddress((void**)&hTx, h_Tx);
    cudaGetSymbolAddress((void**)&hWq, h_Wq);
    cudaGetSymbolAddress((void**)&hWkv, h_Wkv);
    cudaGetSymbolAddress((void**)&hWp, h_Wp);
    cudaGetSymbolAddress((void**)&hQ,  h_Q);
    cudaGetSymbolAddress((void**)&hKV, h_KV);
    cudaGetSymbolAddress((void**)&hP,  h_P);
    cudaGetSymbolAddress((void**)&hO,  h_O);

    constexpr int SMEM_SMALL = STAGE_B * 3;   // 61440
    cudaFuncSetAttribute(hgemm<false, true, 1>, cudaFuncAttributeMaxDynamicSharedMemorySize, SMEM_SMALL);
    cudaFuncSetAttribute(hgemm<true,  true, 2>, cudaFuncAttributeMaxDynamicSharedMemorySize, SMEM_SMALL);
    cudaFuncSetAttribute(hgemm<false, false,1>, cudaFuncAttributeMaxDynamicSharedMemorySize, SMEM_SMALL);
    cudaFuncSetAttribute(hgemm_big<1>, cudaFuncAttributeMaxDynamicSharedMemorySize, BIG_SMEM);
    cudaFuncSetAttribute(hgemm_big<0>, cudaFuncAttributeMaxDynamicSharedMemorySize, BIG_SMEM);

    const float scale = 0.08838834764831843f;  // 1/sqrt(128)

    // 0) fp32 -> fp16
    f2h_all<<<(N4_VX + N4_WQ + N4_WKV + N4_WQ) / 256, 256>>>(
        Vx, Wq, Wkv, Wp, hVx, hWq, hWkv, hWp);
    f2h_pad77<<<NB * CC, 128>>>(Tx, hTx, NB * CC);

    // 1) KV = Wkv @ Tx + bkv : M=2048, N=80(valid 77), K=1024, per-b
    hgemm<false, true, 1><<<dim3(1, 16, NB), 256, SMEM_SMALL>>>(
        hWkv, hTx, hKV, bkv, 2048, TP, CC,
        CC, TP, TP,
        0, 0, (long long)CC * TP, 0,
        (long long)2 * CC * TP, 0, 1, 1.0f, CC, TP, TT);

    // 2) Q = Wq @ Vx + bq : M=1024, N=1024, K=1024, per-b  [BIG]
    hgemm_big<1><<<dim3(8, 4, NB), 512, BIG_SMEM>>>(
        hWq, hVx, hQ, bq, (long long)CC * NN, (long long)CC * NN);

    // 3) P = softmax(scale * Q_h^T K_h) : M=1024(n), N=77(t), K=128, per-(b,h)
    hgemm<true, true, 2><<<dim3(1, 8, NB * NH), 256, SMEM_SMALL>>>(
        hQ, hKV, hP, nullptr, NN, TT, HD,
        NN, TP, TP,
        (long long)CC * NN, (long long)HD * NN,
        (long long)2 * CC * TP, (long long)2 * HD * TP,
        (long long)NH * NN * TP, (long long)NN * TP,
        NH, scale, HD, TP, TT);

    // 4) O = V_h @ P^T : M=128(d), N=1024(n), K=77, per-(b,h)
    hgemm<false, false, 1><<<dim3(8, 1, NB * NH), 256, SMEM_SMALL>>>(
        hKV + (size_t)HD * TP, hP, hO, nullptr, HD, NN, TT,
        TP, TP, NN,
        (long long)2 * CC * TP, (long long)2 * HD * TP,
        (long long)NH * NN * TP, (long long)NN * TP,
        (long long)CC * NN, (long long)HD * NN,
        NH, 1.0f, TP, TP, NN);

    // 5) Y = Wp @ O + bp : M=1024, N=1024, K=1024, per-b, fp32 out  [BIG]
    hgemm_big<0><<<dim3(8, 4, NB), 512, BIG_SMEM>>>(
        hWp, hO, Y, bp, (long long)CC * NN, (long long)CC * NN);
}